// round 14
// baseline (speedup 1.0000x reference)
#include <cuda_runtime.h>
#include <cuda_fp16.h>
#include <cstdint>

#define N_NODES 100000
#define IN_DIM  768
#define OUT_DIM 128
#define MAX_EDGES 1600000

// -------- scratch (device globals; no allocation allowed) --------
__device__ __half d_h[(size_t)N_NODES * OUT_DIM];    // fp16 h = (features@Wd + bd)*norm_src
__device__ float  d_norm_src[N_NODES];
__device__ float  d_norm_dst[N_NODES];
__device__ __half d_Wch[IN_DIM * OUT_DIM];           // (Wg@Wu)^T fp16, [n=768][k=128]
__device__ float  d_bc[IN_DIM];                      // bg @ Wu + bu (fp32)
__device__ __half d_Wdh[OUT_DIM * IN_DIM];           // Wd^T fp16, [n=128][k=768]
__device__ int    d_outdeg[N_NODES];
__device__ int    d_indeg[N_NODES];
__device__ int    d_off[N_NODES + 1];
__device__ int    d_cursor[N_NODES];
__device__ int    d_blocksums[(N_NODES + 1023) / 1024 + 1];
__device__ int    d_edge_src[MAX_EDGES];

// ============ graph/prep kernels ============
__global__ void zero_deg_kernel(int n_nodes) {
    int i = blockIdx.x * blockDim.x + threadIdx.x;
    if (i < n_nodes) { d_outdeg[i] = 0; d_indeg[i] = 0; }
}

__global__ void degree_kernel(const int* __restrict__ src, const int* __restrict__ dst, int n_edges) {
    int i = blockIdx.x * blockDim.x + threadIdx.x;
    if (i < n_edges) {
        atomicAdd(&d_outdeg[src[i]], 1);
        atomicAdd(&d_indeg[dst[i]], 1);
    }
}

__global__ void norm_kernel(int n) {
    int i = blockIdx.x * blockDim.x + threadIdx.x;
    if (i < n) {
        d_norm_src[i] = rsqrtf(fmaxf((float)d_outdeg[i], 1.0f));
        d_norm_dst[i] = rsqrtf(fmaxf((float)d_indeg[i], 1.0f));
    }
}

// Wd^T fp16: d_Wdh[n*768 + k] = (half)Wd[k*128 + n]
__global__ void wdh_kernel(const float* __restrict__ Wd) {
    int i = blockIdx.x * blockDim.x + threadIdx.x;
    if (i < OUT_DIM * IN_DIM) {
        int n = i / IN_DIM;
        int k = i % IN_DIM;
        d_Wdh[i] = __float2half(Wd[(size_t)k * OUT_DIM + n]);
    }
}

__global__ void scan_block_kernel(int n) {
    __shared__ int sh[1024];
    int gid = blockIdx.x * 1024 + threadIdx.x;
    int v = (gid < n) ? d_indeg[gid] : 0;
    sh[threadIdx.x] = v;
    __syncthreads();
    #pragma unroll
    for (int d = 1; d < 1024; d <<= 1) {
        int t = (threadIdx.x >= d) ? sh[threadIdx.x - d] : 0;
        __syncthreads();
        sh[threadIdx.x] += t;
        __syncthreads();
    }
    if (gid < n) d_off[gid] = sh[threadIdx.x] - v;
    if (threadIdx.x == 1023) d_blocksums[blockIdx.x] = sh[1023];
}

__global__ void scan_sums_kernel(int nb) {
    if (threadIdx.x == 0 && blockIdx.x == 0) {
        int acc = 0;
        for (int i = 0; i < nb; i++) { int v = d_blocksums[i]; d_blocksums[i] = acc; acc += v; }
    }
}

__global__ void scan_add_kernel(int n) {
    int gid = blockIdx.x * blockDim.x + threadIdx.x;
    if (gid < n) {
        d_off[gid] += d_blocksums[gid >> 10];
        d_cursor[gid] = 0;
    }
}

__global__ void csr_fill_kernel(const int* __restrict__ src, const int* __restrict__ dst, int n_edges) {
    int e = blockIdx.x * blockDim.x + threadIdx.x;
    if (e < n_edges) {
        int d = dst[e];
        int pos = d_off[d] + atomicAdd(&d_cursor[d], 1);
        d_edge_src[pos] = src[e];
    }
}

// Wc^T fp16: d_Wch[n*128 + k] = (half)(sum_t Wg[k][t]*Wu[t][n]); bc = bg@Wu + bu
__global__ void combine_w_kernel(const float* __restrict__ Wg, const float* __restrict__ bg,
                                 const float* __restrict__ Wu, const float* __restrict__ bu) {
    int idx = blockIdx.x * blockDim.x + threadIdx.x;
    if (idx < IN_DIM * OUT_DIM) {
        int n = idx / OUT_DIM;
        int k = idx % OUT_DIM;
        float acc = 0.0f;
        #pragma unroll 8
        for (int t = 0; t < OUT_DIM; t++)
            acc += Wg[k * OUT_DIM + t] * Wu[t * IN_DIM + n];
        d_Wch[idx] = __float2half(acc);
    }
    if (idx < IN_DIM) {
        float acc = bu[idx];
        #pragma unroll 8
        for (int t = 0; t < OUT_DIM; t++)
            acc += bg[t] * Wu[t * IN_DIM + idx];
        d_bc[idx] = acc;
    }
}

// ================= GEMM1: FP16 mma (m16n8k16), double-buffered (from R13) =================
#define HSK 40   // half stride (32 + 8 pad) for BK=32 tiles

__global__ __launch_bounds__(256)
void h16_gemm1(const float* __restrict__ Af, const __half* __restrict__ B,
               const float* __restrict__ bias, const float* __restrict__ rowscale,
               __half* __restrict__ Ch, int M, int N, int K) {
    __shared__ __half As[2][128 * HSK];
    __shared__ __half Bs[2][128 * HSK];

    const int tid  = threadIdx.x;
    const int lane = tid & 31;
    const int wid  = tid >> 5;
    const int warp_m = (wid >> 2) * 64;
    const int warp_n = (wid & 3) * 32;

    const int brow = blockIdx.y * 128;
    const int bcol = blockIdx.x * 128;

    const int grp = lane >> 2;
    const int tig = lane & 3;

    const int am  = tid >> 1;
    const int akh = (tid & 1) * 16;

    float4 pa[4];
    auto loadA = [&](int k0) {
        const int gr = brow + am;
        if (gr < M) {
            const float* g = Af + (size_t)gr * K + k0 + akh;
            pa[0] = *reinterpret_cast<const float4*>(g);
            pa[1] = *reinterpret_cast<const float4*>(g + 4);
            pa[2] = *reinterpret_cast<const float4*>(g + 8);
            pa[3] = *reinterpret_cast<const float4*>(g + 12);
        } else {
            pa[0] = pa[1] = pa[2] = pa[3] = make_float4(0.f, 0.f, 0.f, 0.f);
        }
    };
    auto storeA = [&](int s) {
        __half2 h[8];
        h[0] = __floats2half2_rn(pa[0].x, pa[0].y);
        h[1] = __floats2half2_rn(pa[0].z, pa[0].w);
        h[2] = __floats2half2_rn(pa[1].x, pa[1].y);
        h[3] = __floats2half2_rn(pa[1].z, pa[1].w);
        h[4] = __floats2half2_rn(pa[2].x, pa[2].y);
        h[5] = __floats2half2_rn(pa[2].z, pa[2].w);
        h[6] = __floats2half2_rn(pa[3].x, pa[3].y);
        h[7] = __floats2half2_rn(pa[3].z, pa[3].w);
        *reinterpret_cast<uint4*>(&As[s][am * HSK + akh])     = *reinterpret_cast<uint4*>(h);
        *reinterpret_cast<uint4*>(&As[s][am * HSK + akh + 8]) = *reinterpret_cast<uint4*>(h + 4);
    };
    auto issueB = [&](int s, int k0) {
        #pragma unroll
        for (int l = 0; l < 2; l++) {
            const int c = tid + l * 256;
            const int n = c >> 2;
            const int kq = (c & 3) * 8;
            const __half* g = B + (size_t)(bcol + n) * K + k0 + kq;
            uint32_t d = (uint32_t)__cvta_generic_to_shared(&Bs[s][n * HSK + kq]);
            asm volatile("cp.async.cg.shared.global [%0], [%1], 16;"
                         :: "r"(d), "l"(g));
        }
    };

    float acc[4][4][4];
    #pragma unroll
    for (int a = 0; a < 4; a++)
        #pragma unroll
        for (int b = 0; b < 4; b++)
            #pragma unroll
            for (int c = 0; c < 4; c++) acc[a][b][c] = 0.f;

    auto compute = [&](int s) {
        #pragma unroll
        for (int kk = 0; kk < 32; kk += 16) {
            uint32_t a[4][4];
            #pragma unroll
            for (int mt = 0; mt < 4; mt++) {
                const int m0 = warp_m + mt * 16;
                a[mt][0] = *reinterpret_cast<const uint32_t*>(&As[s][(m0 + grp    ) * HSK + kk + 2 * tig]);
                a[mt][1] = *reinterpret_cast<const uint32_t*>(&As[s][(m0 + grp + 8) * HSK + kk + 2 * tig]);
                a[mt][2] = *reinterpret_cast<const uint32_t*>(&As[s][(m0 + grp    ) * HSK + kk + 2 * tig + 8]);
                a[mt][3] = *reinterpret_cast<const uint32_t*>(&As[s][(m0 + grp + 8) * HSK + kk + 2 * tig + 8]);
            }
            uint32_t b[4][2];
            #pragma unroll
            for (int nt = 0; nt < 4; nt++) {
                const int n0 = warp_n + nt * 8;
                b[nt][0] = *reinterpret_cast<const uint32_t*>(&Bs[s][(n0 + grp) * HSK + kk + 2 * tig]);
                b[nt][1] = *reinterpret_cast<const uint32_t*>(&Bs[s][(n0 + grp) * HSK + kk + 2 * tig + 8]);
            }
            #pragma unroll
            for (int mt = 0; mt < 4; mt++)
                #pragma unroll
                for (int nt = 0; nt < 4; nt++) {
                    asm volatile(
                        "mma.sync.aligned.m16n8k16.row.col.f32.f16.f16.f32 "
                        "{%0,%1,%2,%3}, {%4,%5,%6,%7}, {%8,%9}, {%0,%1,%2,%3};"
                        : "+f"(acc[mt][nt][0]), "+f"(acc[mt][nt][1]),
                          "+f"(acc[mt][nt][2]), "+f"(acc[mt][nt][3])
                        : "r"(a[mt][0]), "r"(a[mt][1]), "r"(a[mt][2]), "r"(a[mt][3]),
                          "r"(b[nt][0]), "r"(b[nt][1]));
                }
        }
    };

    const int nk = K / 32;
    int buf = 0;
    loadA(0);
    issueB(0, 0);
    asm volatile("cp.async.commit_group;");
    storeA(0);
    asm volatile("cp.async.wait_group 0;");
    __syncthreads();
    for (int t = 0; t < nk; t++) {
        if (t + 1 < nk) {
            loadA((t + 1) * 32);
            issueB(buf ^ 1, (t + 1) * 32);
            asm volatile("cp.async.commit_group;");
        }
        compute(buf);
        if (t + 1 < nk) {
            storeA(buf ^ 1);
            asm volatile("cp.async.wait_group 0;");
            __syncthreads();
        }
        buf ^= 1;
    }

    // epilogue: Ch = half((acc + bias) * rowscale)
    #pragma unroll
    for (int mt = 0; mt < 4; mt++) {
        const int r0 = brow + warp_m + mt * 16 + grp;
        const int r1 = r0 + 8;
        const bool ok0 = (r0 < M);
        const bool ok1 = (r1 < M);
        const float s0 = ok0 ? rowscale[r0] : 0.f;
        const float s1 = ok1 ? rowscale[r1] : 0.f;
        #pragma unroll
        for (int nt = 0; nt < 4; nt++) {
            const int c = bcol + warp_n + nt * 8 + 2 * tig;
            const float bz0 = bias[c], bz1 = bias[c + 1];
            if (ok0)
                *reinterpret_cast<__half2*>(Ch + (size_t)r0 * N + c) =
                    __floats2half2_rn((acc[mt][nt][0] + bz0) * s0, (acc[mt][nt][1] + bz1) * s0);
            if (ok1)
                *reinterpret_cast<__half2*>(Ch + (size_t)r1 * N + c) =
                    __floats2half2_rn((acc[mt][nt][2] + bz0) * s1, (acc[mt][nt][3] + bz1) * s1);
        }
    }
}

// ================= FUSED gather + GEMM2 =================
// Block owns 128 output rows. Phase 1: gather agg rows into smem fp16 [128][AHS].
// Phase 2: 6 n-tiles of Wc (128n x 128k), cp.async double-buffered, mma, epilogue.
#define AHS 136   // half stride for K=128 rows (128 + 8 pad)
#define FUSED_SMEM ((128 * AHS + 2 * 128 * AHS) * (int)sizeof(__half))   // 104448 B

__global__ __launch_bounds__(256)
void fused_gather_gemm2(const __half* __restrict__ Wc,
                        const float* __restrict__ bias, const float* __restrict__ rowscale,
                        float* __restrict__ C, int M) {
    extern __shared__ __half fsm[];
    __half* Ah = fsm;                      // [128][AHS]
    __half* Bs0 = fsm + 128 * AHS;         // [2][128][AHS]

    const int tid  = threadIdx.x;
    const int lane = tid & 31;
    const int wid  = tid >> 5;
    const int warp_m = (wid >> 2) * 64;
    const int warp_n = (wid & 3) * 32;
    const int grp = lane >> 2;
    const int tig = lane & 3;
    const int brow = blockIdx.x * 128;

    auto issueB = [&](int s, int nt6) {
        const __half* base = Wc + (size_t)nt6 * 128 * OUT_DIM;
        __half* bs = Bs0 + s * 128 * AHS;
        #pragma unroll
        for (int l = 0; l < 8; l++) {
            const int c = tid + l * 256;         // 0..2047
            const int n = c >> 4;                // 0..127
            const int kq = (c & 15) * 8;         // 0..120 step 8
            const __half* g = base + (size_t)n * OUT_DIM + kq;
            uint32_t d = (uint32_t)__cvta_generic_to_shared(&bs[n * AHS + kq]);
            asm volatile("cp.async.cg.shared.global [%0], [%1], 16;" :: "r"(d), "l"(g));
        }
        asm volatile("cp.async.commit_group;");
    };

    // prefetch B tile 0 while gathering
    issueB(0, 0);

    // ---- phase 1: gather (one warp per row, rows wid, wid+8, ...) ----
    for (int r = wid; r < 128; r += 8) {
        const int node = brow + r;
        float4 acc = make_float4(0.f, 0.f, 0.f, 0.f);
        if (node < M) {
            const int eb = d_off[node];
            const int cnt = d_indeg[node];
            int j = 0;
            for (; j + 8 <= cnt; j += 8) {
                int s[8];
                #pragma unroll
                for (int u = 0; u < 8; u++) s[u] = d_edge_src[eb + j + u];
                uint2 v[8];
                #pragma unroll
                for (int u = 0; u < 8; u++)
                    v[u] = *reinterpret_cast<const uint2*>(d_h + (size_t)s[u] * OUT_DIM + lane * 4);
                #pragma unroll
                for (int u = 0; u < 8; u++) {
                    float2 f0 = __half22float2(*reinterpret_cast<__half2*>(&v[u].x));
                    float2 f1 = __half22float2(*reinterpret_cast<__half2*>(&v[u].y));
                    acc.x += f0.x; acc.y += f0.y; acc.z += f1.x; acc.w += f1.y;
                }
            }
            for (; j < cnt; j++) {
                const int s = d_edge_src[eb + j];
                uint2 v = *reinterpret_cast<const uint2*>(d_h + (size_t)s * OUT_DIM + lane * 4);
                float2 f0 = __half22float2(*reinterpret_cast<__half2*>(&v.x));
                float2 f1 = __half22float2(*reinterpret_cast<__half2*>(&v.y));
                acc.x += f0.x; acc.y += f0.y; acc.z += f1.x; acc.w += f1.y;
            }
        }
        uint2 o;
        *reinterpret_cast<__half2*>(&o.x) = __floats2half2_rn(acc.x, acc.y);
        *reinterpret_cast<__half2*>(&o.y) = __floats2half2_rn(acc.z, acc.w);
        *reinterpret_cast<uint2*>(&Ah[r * AHS + lane * 4]) = o;
    }
    __syncthreads();

    // ---- phase 2: 6 n-tiles ----
    int buf = 0;
    #pragma unroll 1
    for (int nt6 = 0; nt6 < IN_DIM / 128; nt6++) {
        if (nt6 + 1 < IN_DIM / 128) {
            asm volatile("cp.async.wait_group 0;");   // tile nt6 ready
            __syncthreads();
            issueB(buf ^ 1, nt6 + 1);
        } else {
            asm volatile("cp.async.wait_group 0;");
            __syncthreads();
        }

        const __half* bs = Bs0 + buf * 128 * AHS;

        float acc[4][4][4];
        #pragma unroll
        for (int a = 0; a < 4; a++)
            #pragma unroll
            for (int b = 0; b < 4; b++)
                #pragma unroll
                for (int c = 0; c < 4; c++) acc[a][b][c] = 0.f;

        #pragma unroll
        for (int kk = 0; kk < 128; kk += 16) {
            uint32_t a[4][4];
            #pragma unroll
            for (int mt = 0; mt < 4; mt++) {
                const int m0 = warp_m + mt * 16;
                a[mt][0] = *reinterpret_cast<const uint32_t*>(&Ah[(m0 + grp    ) * AHS + kk + 2 * tig]);
                a[mt][1] = *reinterpret_cast<const uint32_t*>(&Ah[(m0 + grp + 8) * AHS + kk + 2 * tig]);
                a[mt][2] = *reinterpret_cast<const uint32_t*>(&Ah[(m0 + grp    ) * AHS + kk + 2 * tig + 8]);
                a[mt][3] = *reinterpret_cast<const uint32_t*>(&Ah[(m0 + grp + 8) * AHS + kk + 2 * tig + 8]);
            }
            uint32_t b[4][2];
            #pragma unroll
            for (int nt = 0; nt < 4; nt++) {
                const int n0 = warp_n + nt * 8;
                b[nt][0] = *reinterpret_cast<const uint32_t*>(&bs[(n0 + grp) * AHS + kk + 2 * tig]);
                b[nt][1] = *reinterpret_cast<const uint32_t*>(&bs[(n0 + grp) * AHS + kk + 2 * tig + 8]);
            }
            #pragma unroll
            for (int mt = 0; mt < 4; mt++)
                #pragma unroll
                for (int nt = 0; nt < 4; nt++) {
                    asm volatile(
                        "mma.sync.aligned.m16n8k16.row.col.f32.f16.f16.f32 "
                        "{%0,%1,%2,%3}, {%4,%5,%6,%7}, {%8,%9}, {%0,%1,%2,%3};"
                        : "+f"(acc[mt][nt][0]), "+f"(acc[mt][nt][1]),
                          "+f"(acc[mt][nt][2]), "+f"(acc[mt][nt][3])
                        : "r"(a[mt][0]), "r"(a[mt][1]), "r"(a[mt][2]), "r"(a[mt][3]),
                          "r"(b[nt][0]), "r"(b[nt][1]));
                }
        }

        // epilogue for this n-tile: C = acc*rowscale + bias
        const int cbase = nt6 * 128;
        #pragma unroll
        for (int mt = 0; mt < 4; mt++) {
            const int r0 = brow + warp_m + mt * 16 + grp;
            const int r1 = r0 + 8;
            const bool ok0 = (r0 < M);
            const bool ok1 = (r1 < M);
            const float s0 = ok0 ? rowscale[r0] : 0.f;
            const float s1 = ok1 ? rowscale[r1] : 0.f;
            #pragma unroll
            for (int nt = 0; nt < 4; nt++) {
                const int c = cbase + warp_n + nt * 8 + 2 * tig;
                const float bz0 = bias[c], bz1 = bias[c + 1];
                if (ok0)
                    *reinterpret_cast<float2*>(C + (size_t)r0 * IN_DIM + c) =
                        make_float2(fmaf(acc[mt][nt][0], s0, bz0), fmaf(acc[mt][nt][1], s0, bz1));
                if (ok1)
                    *reinterpret_cast<float2*>(C + (size_t)r1 * IN_DIM + c) =
                        make_float2(fmaf(acc[mt][nt][2], s1, bz0), fmaf(acc[mt][nt][3], s1, bz1));
            }
        }
        if (nt6 + 1 < IN_DIM / 128) __syncthreads();   // before overwriting buf on next issue
        buf ^= 1;
    }
}

extern "C" void kernel_launch(void* const* d_in, const int* in_sizes, int n_in,
                              void* d_out, int out_size) {
    const float* features = (const float*)d_in[0];
    const float* Wd       = (const float*)d_in[1];
    const float* bd       = (const float*)d_in[2];
    const float* Wg       = (const float*)d_in[3];
    const float* bg       = (const float*)d_in[4];
    const float* Wu       = (const float*)d_in[5];
    const float* bu       = (const float*)d_in[6];
    const int*   src      = (const int*)d_in[7];
    const int*   dst      = (const int*)d_in[8];
    float*       out      = (float*)d_out;

    const int n_nodes = in_sizes[0] / IN_DIM;
    const int n_edges = in_sizes[7];

    static __half* p_h = nullptr;
    static float* p_ns = nullptr; static float* p_nd = nullptr;
    static __half* p_Wch = nullptr; static float* p_bc = nullptr;
    static __half* p_Wdh = nullptr;
    static cudaStream_t s1;
    static cudaEvent_t ev_deg, ev_csr;
    if (!p_h) {
        cudaGetSymbolAddress((void**)&p_h,   d_h);
        cudaGetSymbolAddress((void**)&p_ns,  d_norm_src);
        cudaGetSymbolAddress((void**)&p_nd,  d_norm_dst);
        cudaGetSymbolAddress((void**)&p_Wch, d_Wch);
        cudaGetSymbolAddress((void**)&p_bc,  d_bc);
        cudaGetSymbolAddress((void**)&p_Wdh, d_Wdh);
        cudaStreamCreateWithFlags(&s1, cudaStreamNonBlocking);
        cudaEventCreateWithFlags(&ev_deg, cudaEventDisableTiming);
        cudaEventCreateWithFlags(&ev_csr, cudaEventDisableTiming);
        cudaFuncSetAttribute(fused_gather_gemm2,
                             cudaFuncAttributeMaxDynamicSharedMemorySize, FUSED_SMEM);
    }

    const int nscan_blocks = (n_nodes + 1023) / 1024;

    // main stream: degrees -> norms, Wd transpose+convert
    zero_deg_kernel<<<(n_nodes + 255) / 256, 256>>>(n_nodes);
    degree_kernel<<<(n_edges + 255) / 256, 256>>>(src, dst, n_edges);
    norm_kernel<<<(n_nodes + 255) / 256, 256>>>(n_nodes);
    wdh_kernel<<<(OUT_DIM * IN_DIM + 255) / 256, 256>>>(Wd);
    cudaEventRecord(ev_deg, 0);

    // side stream: CSR build + combine_w, concurrent with GEMM1
    cudaStreamWaitEvent(s1, ev_deg, 0);
    scan_block_kernel<<<nscan_blocks, 1024, 0, s1>>>(n_nodes);
    scan_sums_kernel<<<1, 32, 0, s1>>>(nscan_blocks);
    scan_add_kernel<<<(n_nodes + 255) / 256, 256, 0, s1>>>(n_nodes);
    csr_fill_kernel<<<(n_edges + 255) / 256, 256, 0, s1>>>(src, dst, n_edges);
    combine_w_kernel<<<(IN_DIM * OUT_DIM + 255) / 256, 256, 0, s1>>>(Wg, bg, Wu, bu);
    cudaEventRecord(ev_csr, s1);

    // GEMM1: h = half( (features @ Wd + bd) * norm_src )   [N,128] fp16
    {
        dim3 grid(OUT_DIM / 128, (n_nodes + 127) / 128);
        h16_gemm1<<<grid, 256>>>(features, p_Wdh, bd, p_ns, p_h, n_nodes, OUT_DIM, IN_DIM);
    }

    // join, then FUSED gather + GEMM2: out = (gather(h) @ Wc) * norm_dst + bc
    cudaStreamWaitEvent(0, ev_csr, 0);
    fused_gather_gemm2<<<(n_nodes + 127) / 128, 256, FUSED_SMEM>>>(p_Wch, p_bc, p_nd, out, n_nodes);
}

// round 15
// speedup vs baseline: 1.1127x; 1.1127x over previous
#include <cuda_runtime.h>
#include <cuda_fp16.h>
#include <cstdint>

#define N_NODES 100000
#define IN_DIM  768
#define OUT_DIM 128
#define MAX_EDGES 1600000

// -------- scratch (device globals; no allocation allowed) --------
__device__ __half d_h[(size_t)N_NODES * OUT_DIM];    // fp16 h = (features@Wd + bd)*norm_src
__device__ __half d_agg[(size_t)N_NODES * OUT_DIM];  // fp16 gather result
__device__ float  d_norm_src[N_NODES];
__device__ float  d_norm_dst[N_NODES];
__device__ __half d_Wch[IN_DIM * OUT_DIM];           // (Wg@Wu)^T fp16, [n=768][k=128]
__device__ float  d_bc[IN_DIM];                      // bg @ Wu + bu (fp32)
__device__ __half d_Wdh[OUT_DIM * IN_DIM];           // Wd^T fp16, [n=128][k=768]
__device__ int    d_outdeg[N_NODES];
__device__ int    d_indeg[N_NODES];
__device__ int    d_off[N_NODES + 1];
__device__ int    d_cursor[N_NODES];
__device__ int    d_blocksums[(N_NODES + 1023) / 1024 + 1];
__device__ int    d_edge_src[MAX_EDGES];

// ============ graph/prep kernels ============
__global__ void zero_deg_kernel(int n_nodes) {
    int i = blockIdx.x * blockDim.x + threadIdx.x;
    if (i < n_nodes) { d_outdeg[i] = 0; d_indeg[i] = 0; }
}

__global__ void degree_kernel(const int* __restrict__ src, const int* __restrict__ dst, int n_edges) {
    int i = blockIdx.x * blockDim.x + threadIdx.x;
    if (i < n_edges) {
        atomicAdd(&d_outdeg[src[i]], 1);
        atomicAdd(&d_indeg[dst[i]], 1);
    }
}

__global__ void norm_kernel(int n) {
    int i = blockIdx.x * blockDim.x + threadIdx.x;
    if (i < n) {
        d_norm_src[i] = rsqrtf(fmaxf((float)d_outdeg[i], 1.0f));
        d_norm_dst[i] = rsqrtf(fmaxf((float)d_indeg[i], 1.0f));
    }
}

// Wd^T fp16: d_Wdh[n*768 + k] = (half)Wd[k*128 + n]
__global__ void wdh_kernel(const float* __restrict__ Wd) {
    int i = blockIdx.x * blockDim.x + threadIdx.x;
    if (i < OUT_DIM * IN_DIM) {
        int n = i / IN_DIM;
        int k = i % IN_DIM;
        d_Wdh[i] = __float2half(Wd[(size_t)k * OUT_DIM + n]);
    }
}

__global__ void scan_block_kernel(int n) {
    __shared__ int sh[1024];
    int gid = blockIdx.x * 1024 + threadIdx.x;
    int v = (gid < n) ? d_indeg[gid] : 0;
    sh[threadIdx.x] = v;
    __syncthreads();
    #pragma unroll
    for (int d = 1; d < 1024; d <<= 1) {
        int t = (threadIdx.x >= d) ? sh[threadIdx.x - d] : 0;
        __syncthreads();
        sh[threadIdx.x] += t;
        __syncthreads();
    }
    if (gid < n) d_off[gid] = sh[threadIdx.x] - v;
    if (threadIdx.x == 1023) d_blocksums[blockIdx.x] = sh[1023];
}

__global__ void scan_sums_kernel(int nb) {
    if (threadIdx.x == 0 && blockIdx.x == 0) {
        int acc = 0;
        for (int i = 0; i < nb; i++) { int v = d_blocksums[i]; d_blocksums[i] = acc; acc += v; }
    }
}

__global__ void scan_add_kernel(int n) {
    int gid = blockIdx.x * blockDim.x + threadIdx.x;
    if (gid < n) {
        d_off[gid] += d_blocksums[gid >> 10];
        d_cursor[gid] = 0;
    }
}

__global__ void csr_fill_kernel(const int* __restrict__ src, const int* __restrict__ dst, int n_edges) {
    int e = blockIdx.x * blockDim.x + threadIdx.x;
    if (e < n_edges) {
        int d = dst[e];
        int pos = d_off[d] + atomicAdd(&d_cursor[d], 1);
        d_edge_src[pos] = src[e];
    }
}

// Wc^T fp16: d_Wch[n*128 + k] = (half)(sum_t Wg[k][t]*Wu[t][n]); bc = bg@Wu + bu
__global__ void combine_w_kernel(const float* __restrict__ Wg, const float* __restrict__ bg,
                                 const float* __restrict__ Wu, const float* __restrict__ bu) {
    int idx = blockIdx.x * blockDim.x + threadIdx.x;
    if (idx < IN_DIM * OUT_DIM) {
        int n = idx / OUT_DIM;
        int k = idx % OUT_DIM;
        float acc = 0.0f;
        #pragma unroll 8
        for (int t = 0; t < OUT_DIM; t++)
            acc += Wg[k * OUT_DIM + t] * Wu[t * IN_DIM + n];
        d_Wch[idx] = __float2half(acc);
    }
    if (idx < IN_DIM) {
        float acc = bu[idx];
        #pragma unroll 8
        for (int t = 0; t < OUT_DIM; t++)
            acc += bg[t] * Wu[t * IN_DIM + idx];
        d_bc[idx] = acc;
    }
}

// -------- gather over [beg,end): agg[v] = half( sum h[src[e]] ), warp/node, ILP 8 --------
__global__ void gather_kernel(int beg, int end) {
    const int node = beg + blockIdx.x * (blockDim.x >> 5) + (threadIdx.x >> 5);
    const int lane = threadIdx.x & 31;
    if (node >= end) return;
    const int eb = d_off[node];
    const int cnt = d_indeg[node];

    float4 acc = make_float4(0.f, 0.f, 0.f, 0.f);
    int j = 0;
    for (; j + 8 <= cnt; j += 8) {
        int s[8];
        #pragma unroll
        for (int u = 0; u < 8; u++) s[u] = d_edge_src[eb + j + u];
        uint2 v[8];
        #pragma unroll
        for (int u = 0; u < 8; u++)
            v[u] = *reinterpret_cast<const uint2*>(d_h + (size_t)s[u] * OUT_DIM + lane * 4);
        #pragma unroll
        for (int u = 0; u < 8; u++) {
            float2 f0 = __half22float2(*reinterpret_cast<__half2*>(&v[u].x));
            float2 f1 = __half22float2(*reinterpret_cast<__half2*>(&v[u].y));
            acc.x += f0.x; acc.y += f0.y; acc.z += f1.x; acc.w += f1.y;
        }
    }
    for (; j < cnt; j++) {
        const int s = d_edge_src[eb + j];
        uint2 v = *reinterpret_cast<const uint2*>(d_h + (size_t)s * OUT_DIM + lane * 4);
        float2 f0 = __half22float2(*reinterpret_cast<__half2*>(&v.x));
        float2 f1 = __half22float2(*reinterpret_cast<__half2*>(&v.y));
        acc.x += f0.x; acc.y += f0.y; acc.z += f1.x; acc.w += f1.y;
    }
    uint2 o;
    *reinterpret_cast<__half2*>(&o.x) = __floats2half2_rn(acc.x, acc.y);
    *reinterpret_cast<__half2*>(&o.y) = __floats2half2_rn(acc.z, acc.w);
    *reinterpret_cast<uint2*>(d_agg + (size_t)node * OUT_DIM + lane * 4) = o;
}

// ================= FP16 tensor-core GEMM (m16n8k16), double-buffered =================
#define HSK 40   // half stride (32 + 8 pad)

template<bool SCALE_AFTER_BIAS, bool CVT_A, bool OUT_HALF>
__global__ __launch_bounds__(256)
void h16_gemm(const float* __restrict__ Af, const __half* __restrict__ Ah,
              const __half* __restrict__ B,
              const float* __restrict__ bias, const float* __restrict__ rowscale,
              float* __restrict__ Cf, __half* __restrict__ Ch,
              int M, int N, int K) {
    __shared__ __half As[2][128 * HSK];
    __shared__ __half Bs[2][128 * HSK];

    const int tid  = threadIdx.x;
    const int lane = tid & 31;
    const int wid  = tid >> 5;
    const int warp_m = (wid >> 2) * 64;
    const int warp_n = (wid & 3) * 32;

    const int brow = blockIdx.y * 128;
    const int bcol = blockIdx.x * 128;

    const int grp = lane >> 2;
    const int tig = lane & 3;

    const int am  = tid >> 1;
    const int akh = (tid & 1) * 16;

    float4 pa[4];
    auto loadA = [&](int k0) {
        const int gr = brow + am;
        if (gr < M) {
            const float* g = Af + (size_t)gr * K + k0 + akh;
            pa[0] = *reinterpret_cast<const float4*>(g);
            pa[1] = *reinterpret_cast<const float4*>(g + 4);
            pa[2] = *reinterpret_cast<const float4*>(g + 8);
            pa[3] = *reinterpret_cast<const float4*>(g + 12);
        } else {
            pa[0] = pa[1] = pa[2] = pa[3] = make_float4(0.f, 0.f, 0.f, 0.f);
        }
    };
    auto storeA = [&](int s) {
        __half2 h[8];
        h[0] = __floats2half2_rn(pa[0].x, pa[0].y);
        h[1] = __floats2half2_rn(pa[0].z, pa[0].w);
        h[2] = __floats2half2_rn(pa[1].x, pa[1].y);
        h[3] = __floats2half2_rn(pa[1].z, pa[1].w);
        h[4] = __floats2half2_rn(pa[2].x, pa[2].y);
        h[5] = __floats2half2_rn(pa[2].z, pa[2].w);
        h[6] = __floats2half2_rn(pa[3].x, pa[3].y);
        h[7] = __floats2half2_rn(pa[3].z, pa[3].w);
        *reinterpret_cast<uint4*>(&As[s][am * HSK + akh])     = *reinterpret_cast<uint4*>(h);
        *reinterpret_cast<uint4*>(&As[s][am * HSK + akh + 8]) = *reinterpret_cast<uint4*>(h + 4);
    };

    auto issueA16 = [&](int s, int k0) {
        #pragma unroll
        for (int l = 0; l < 2; l++) {
            const int c = tid + l * 256;
            const int m = c >> 2;
            const int kq = (c & 3) * 8;
            const __half* g = Ah + (size_t)(brow + m) * K + k0 + kq;
            uint32_t d = (uint32_t)__cvta_generic_to_shared(&As[s][m * HSK + kq]);
            int vb = (brow + m < M) ? 16 : 0;
            asm volatile("cp.async.cg.shared.global [%0], [%1], 16, %2;"
                         :: "r"(d), "l"(g), "r"(vb));
        }
    };
    auto issueB = [&](int s, int k0) {
        #pragma unroll
        for (int l = 0; l < 2; l++) {
            const int c = tid + l * 256;
            const int n = c >> 2;
            const int kq = (c & 3) * 8;
            const __half* g = B + (size_t)(bcol + n) * K + k0 + kq;
            uint32_t d = (uint32_t)__cvta_generic_to_shared(&Bs[s][n * HSK + kq]);
            asm volatile("cp.async.cg.shared.global [%0], [%1], 16;"
                         :: "r"(d), "l"(g));
        }
    };

    float acc[4][4][4];
    #pragma unroll
    for (int a = 0; a < 4; a++)
        #pragma unroll
        for (int b = 0; b < 4; b++)
            #pragma unroll
            for (int c = 0; c < 4; c++) acc[a][b][c] = 0.f;

    auto compute = [&](int s) {
        #pragma unroll
        for (int kk = 0; kk < 32; kk += 16) {
            uint32_t a[4][4];
            #pragma unroll
            for (int mt = 0; mt < 4; mt++) {
                const int m0 = warp_m + mt * 16;
                a[mt][0] = *reinterpret_cast<const uint32_t*>(&As[s][(m0 + grp    ) * HSK + kk + 2 * tig]);
                a[mt][1] = *reinterpret_cast<const uint32_t*>(&As[s][(m0 + grp + 8) * HSK + kk + 2 * tig]);
                a[mt][2] = *reinterpret_cast<const uint32_t*>(&As[s][(m0 + grp    ) * HSK + kk + 2 * tig + 8]);
                a[mt][3] = *reinterpret_cast<const uint32_t*>(&As[s][(m0 + grp + 8) * HSK + kk + 2 * tig + 8]);
            }
            uint32_t b[4][2];
            #pragma unroll
            for (int nt = 0; nt < 4; nt++) {
                const int n0 = warp_n + nt * 8;
                b[nt][0] = *reinterpret_cast<const uint32_t*>(&Bs[s][(n0 + grp) * HSK + kk + 2 * tig]);
                b[nt][1] = *reinterpret_cast<const uint32_t*>(&Bs[s][(n0 + grp) * HSK + kk + 2 * tig + 8]);
            }
            #pragma unroll
            for (int mt = 0; mt < 4; mt++)
                #pragma unroll
                for (int nt = 0; nt < 4; nt++) {
                    asm volatile(
                        "mma.sync.aligned.m16n8k16.row.col.f32.f16.f16.f32 "
                        "{%0,%1,%2,%3}, {%4,%5,%6,%7}, {%8,%9}, {%0,%1,%2,%3};"
                        : "+f"(acc[mt][nt][0]), "+f"(acc[mt][nt][1]),
                          "+f"(acc[mt][nt][2]), "+f"(acc[mt][nt][3])
                        : "r"(a[mt][0]), "r"(a[mt][1]), "r"(a[mt][2]), "r"(a[mt][3]),
                          "r"(b[nt][0]), "r"(b[nt][1]));
                }
        }
    };

    const int nk = K / 32;
    int buf = 0;
    if (CVT_A) {
        loadA(0);
        issueB(0, 0);
        asm volatile("cp.async.commit_group;");
        storeA(0);
        asm volatile("cp.async.wait_group 0;");
        __syncthreads();
        for (int t = 0; t < nk; t++) {
            if (t + 1 < nk) {
                loadA((t + 1) * 32);
                issueB(buf ^ 1, (t + 1) * 32);
                asm volatile("cp.async.commit_group;");
            }
            compute(buf);
            if (t + 1 < nk) {
                storeA(buf ^ 1);
                asm volatile("cp.async.wait_group 0;");
                __syncthreads();
            }
            buf ^= 1;
        }
    } else {
        issueA16(0, 0);
        issueB(0, 0);
        asm volatile("cp.async.commit_group;");
        asm volatile("cp.async.wait_group 0;");
        __syncthreads();
        for (int t = 0; t < nk; t++) {
            if (t + 1 < nk) {
                issueA16(buf ^ 1, (t + 1) * 32);
                issueB(buf ^ 1, (t + 1) * 32);
                asm volatile("cp.async.commit_group;");
            }
            compute(buf);
            if (t + 1 < nk) {
                asm volatile("cp.async.wait_group 0;");
                __syncthreads();
            }
            buf ^= 1;
        }
    }

    // ---- epilogue ----
    #pragma unroll
    for (int mt = 0; mt < 4; mt++) {
        const int r0 = brow + warp_m + mt * 16 + grp;
        const int r1 = r0 + 8;
        const bool ok0 = (r0 < M);
        const bool ok1 = (r1 < M);
        const float s0 = ok0 ? rowscale[r0] : 0.f;
        const float s1 = ok1 ? rowscale[r1] : 0.f;
        #pragma unroll
        for (int nt = 0; nt < 4; nt++) {
            const int c = bcol + warp_n + nt * 8 + 2 * tig;
            const float bz0 = bias[c], bz1 = bias[c + 1];
            float ox0, oy0, ox1, oy1;
            if (SCALE_AFTER_BIAS) {
                ox0 = (acc[mt][nt][0] + bz0) * s0;
                oy0 = (acc[mt][nt][1] + bz1) * s0;
                ox1 = (acc[mt][nt][2] + bz0) * s1;
                oy1 = (acc[mt][nt][3] + bz1) * s1;
            } else {
                ox0 = fmaf(acc[mt][nt][0], s0, bz0);
                oy0 = fmaf(acc[mt][nt][1], s0, bz1);
                ox1 = fmaf(acc[mt][nt][2], s1, bz0);
                oy1 = fmaf(acc[mt][nt][3], s1, bz1);
            }
            if (OUT_HALF) {
                if (ok0)
                    *reinterpret_cast<__half2*>(Ch + (size_t)r0 * N + c) = __floats2half2_rn(ox0, oy0);
                if (ok1)
                    *reinterpret_cast<__half2*>(Ch + (size_t)r1 * N + c) = __floats2half2_rn(ox1, oy1);
            } else {
                if (ok0)
                    *reinterpret_cast<float2*>(Cf + (size_t)r0 * N + c) = make_float2(ox0, oy0);
                if (ok1)
                    *reinterpret_cast<float2*>(Cf + (size_t)r1 * N + c) = make_float2(ox1, oy1);
            }
        }
    }
}

extern "C" void kernel_launch(void* const* d_in, const int* in_sizes, int n_in,
                              void* d_out, int out_size) {
    const float* features = (const float*)d_in[0];
    const float* Wd       = (const float*)d_in[1];
    const float* bd       = (const float*)d_in[2];
    const float* Wg       = (const float*)d_in[3];
    const float* bg       = (const float*)d_in[4];
    const float* Wu       = (const float*)d_in[5];
    const float* bu       = (const float*)d_in[6];
    const int*   src      = (const int*)d_in[7];
    const int*   dst      = (const int*)d_in[8];
    float*       out      = (float*)d_out;

    const int n_nodes = in_sizes[0] / IN_DIM;
    const int n_edges = in_sizes[7];

    static __half* p_h = nullptr; static __half* p_agg = nullptr;
    static float* p_ns = nullptr; static float* p_nd = nullptr;
    static __half* p_Wch = nullptr; static float* p_bc = nullptr;
    static __half* p_Wdh = nullptr;
    static cudaStream_t s1;
    static cudaEvent_t ev_deg, ev_csr, ev_g0, ev_g1, ev_g2;
    if (!p_h) {
        cudaGetSymbolAddress((void**)&p_h,   d_h);
        cudaGetSymbolAddress((void**)&p_agg, d_agg);
        cudaGetSymbolAddress((void**)&p_ns,  d_norm_src);
        cudaGetSymbolAddress((void**)&p_nd,  d_norm_dst);
        cudaGetSymbolAddress((void**)&p_Wch, d_Wch);
        cudaGetSymbolAddress((void**)&p_bc,  d_bc);
        cudaGetSymbolAddress((void**)&p_Wdh, d_Wdh);
        cudaStreamCreateWithFlags(&s1, cudaStreamNonBlocking);
        cudaEventCreateWithFlags(&ev_deg, cudaEventDisableTiming);
        cudaEventCreateWithFlags(&ev_csr, cudaEventDisableTiming);
        cudaEventCreateWithFlags(&ev_g0, cudaEventDisableTiming);
        cudaEventCreateWithFlags(&ev_g1, cudaEventDisableTiming);
        cudaEventCreateWithFlags(&ev_g2, cudaEventDisableTiming);
    }

    const int nscan_blocks = (n_nodes + 1023) / 1024;

    // chunk boundaries (multiples of 128)
    const int c1 = ((n_nodes / 3) + 127) & ~127;          // ~33408
    const int c2 = ((2 * n_nodes / 3) + 127) & ~127;      // ~66816

    // main stream: degrees -> norms, Wd transpose+convert
    zero_deg_kernel<<<(n_nodes + 255) / 256, 256>>>(n_nodes);
    degree_kernel<<<(n_edges + 255) / 256, 256>>>(src, dst, n_edges);
    norm_kernel<<<(n_nodes + 255) / 256, 256>>>(n_nodes);
    wdh_kernel<<<(OUT_DIM * IN_DIM + 255) / 256, 256>>>(Wd);
    cudaEventRecord(ev_deg, 0);

    // side stream: CSR build + combine_w, concurrent with GEMM1
    cudaStreamWaitEvent(s1, ev_deg, 0);
    scan_block_kernel<<<nscan_blocks, 1024, 0, s1>>>(n_nodes);
    scan_sums_kernel<<<1, 32, 0, s1>>>(nscan_blocks);
    scan_add_kernel<<<(n_nodes + 255) / 256, 256, 0, s1>>>(n_nodes);
    csr_fill_kernel<<<(n_edges + 255) / 256, 256, 0, s1>>>(src, dst, n_edges);
    combine_w_kernel<<<(IN_DIM * OUT_DIM + 255) / 256, 256, 0, s1>>>(Wg, bg, Wu, bu);
    cudaEventRecord(ev_csr, s1);

    // GEMM1: h = half( (features @ Wd + bd) * norm_src )   [N,128] fp16
    {
        dim3 grid(OUT_DIM / 128, (n_nodes + 127) / 128);
        h16_gemm<true, true, true><<<grid, 256>>>(
            features, nullptr, p_Wdh, bd, p_ns, nullptr, p_h, n_nodes, OUT_DIM, IN_DIM);
    }

    // ---- chunked gather / GEMM2 pipeline ----
    // main: gather(c0)
    cudaStreamWaitEvent(0, ev_csr, 0);
    gather_kernel<<<(c1 + 7) / 8, 256>>>(0, c1);
    cudaEventRecord(ev_g0, 0);

    // s1: gather(c1) then gather(c2), sequenced after gather(c0)
    cudaStreamWaitEvent(s1, ev_g0, 0);
    gather_kernel<<<(c2 - c1 + 7) / 8, 256, 0, s1>>>(c1, c2);
    cudaEventRecord(ev_g1, s1);
    gather_kernel<<<(n_nodes - c2 + 7) / 8, 256, 0, s1>>>(c2, n_nodes);
    cudaEventRecord(ev_g2, s1);

    // main: GEMM2 chunk0 (overlaps gather c1/c2)
    {
        dim3 grid(IN_DIM / 128, c1 / 128);
        h16_gemm<false, false, false><<<grid, 256>>>(
            nullptr, p_agg, p_Wch, p_bc, p_nd, out, nullptr, c1, IN_DIM, OUT_DIM);
    }
    // main: GEMM2 chunk1
    cudaStreamWaitEvent(0, ev_g1, 0);
    {
        dim3 grid(IN_DIM / 128, (c2 - c1) / 128);
        h16_gemm<false, false, false><<<grid, 256>>>(
            nullptr, p_agg + (size_t)c1 * OUT_DIM, p_Wch, p_bc, p_nd + c1,
            out + (size_t)c1 * IN_DIM, nullptr, c2 - c1, IN_DIM, OUT_DIM);
    }
    // main: GEMM2 chunk2
    cudaStreamWaitEvent(0, ev_g2, 0);
    {
        dim3 grid(IN_DIM / 128, (n_nodes - c2 + 127) / 128);
        h16_gemm<false, false, false><<<grid, 256>>>(
            nullptr, p_agg + (size_t)c2 * OUT_DIM, p_Wch, p_bc, p_nd + c2,
            out + (size_t)c2 * IN_DIM, nullptr, n_nodes - c2, IN_DIM, OUT_DIM);
    }
}

// round 16
// speedup vs baseline: 1.2951x; 1.1639x over previous
#include <cuda_runtime.h>
#include <cuda_fp16.h>
#include <cstdint>

#define N_NODES 100000
#define IN_DIM  768
#define OUT_DIM 128
#define MAX_EDGES 1600000

// -------- scratch (device globals; no allocation allowed) --------
__device__ __half d_h[(size_t)N_NODES * OUT_DIM];    // fp16 h = (features@Wd + bd)*norm_src
__device__ __half d_agg[(size_t)N_NODES * OUT_DIM];  // fp16 gather result
__device__ __half d_Wch[IN_DIM * OUT_DIM];           // (Wg@Wu)^T fp16, [n=768][k=128]
__device__ float  d_bc[IN_DIM];                      // bg @ Wu + bu (fp32)
__device__ __half d_Wdh[OUT_DIM * IN_DIM];           // Wd^T fp16, [n=128][k=768]
__device__ int    d_outdeg[N_NODES];
__device__ int    d_indeg[N_NODES];
__device__ int    d_off[N_NODES + 1];
__device__ int    d_cursor[N_NODES];
__device__ int    d_blocksums[(N_NODES + 1023) / 1024 + 1];
__device__ int    d_edge_src[MAX_EDGES];

// ============ graph/prep kernels ============
__global__ void zero_deg_kernel(int n_nodes) {
    int i = blockIdx.x * blockDim.x + threadIdx.x;
    if (i < n_nodes) { d_outdeg[i] = 0; d_indeg[i] = 0; }
}

__global__ void degree_kernel(const int* __restrict__ src, const int* __restrict__ dst, int n_edges) {
    int i = blockIdx.x * blockDim.x + threadIdx.x;
    if (i < n_edges) {
        atomicAdd(&d_outdeg[src[i]], 1);
        atomicAdd(&d_indeg[dst[i]], 1);
    }
}

// Wd^T fp16: d_Wdh[n*768 + k] = (half)Wd[k*128 + n]
__global__ void wdh_kernel(const float* __restrict__ Wd) {
    int i = blockIdx.x * blockDim.x + threadIdx.x;
    if (i < OUT_DIM * IN_DIM) {
        int n = i / IN_DIM;
        int k = i % IN_DIM;
        d_Wdh[i] = __float2half(Wd[(size_t)k * OUT_DIM + n]);
    }
}

__global__ void scan_block_kernel(int n) {
    __shared__ int sh[1024];
    int gid = blockIdx.x * 1024 + threadIdx.x;
    int v = (gid < n) ? d_indeg[gid] : 0;
    sh[threadIdx.x] = v;
    __syncthreads();
    #pragma unroll
    for (int d = 1; d < 1024; d <<= 1) {
        int t = (threadIdx.x >= d) ? sh[threadIdx.x - d] : 0;
        __syncthreads();
        sh[threadIdx.x] += t;
        __syncthreads();
    }
    if (gid < n) d_off[gid] = sh[threadIdx.x] - v;
    if (threadIdx.x == 1023) d_blocksums[blockIdx.x] = sh[1023];
}

__global__ void scan_sums_kernel(int nb) {
    if (threadIdx.x == 0 && blockIdx.x == 0) {
        int acc = 0;
        for (int i = 0; i < nb; i++) { int v = d_blocksums[i]; d_blocksums[i] = acc; acc += v; }
    }
}

__global__ void scan_add_kernel(int n) {
    int gid = blockIdx.x * blockDim.x + threadIdx.x;
    if (gid < n) {
        d_off[gid] += d_blocksums[gid >> 10];
        d_cursor[gid] = 0;
    }
}

__global__ void csr_fill_kernel(const int* __restrict__ src, const int* __restrict__ dst, int n_edges) {
    int e = blockIdx.x * blockDim.x + threadIdx.x;
    if (e < n_edges) {
        int d = dst[e];
        int pos = d_off[d] + atomicAdd(&d_cursor[d], 1);
        d_edge_src[pos] = src[e];
    }
}

// Wc^T fp16: d_Wch[n*128 + k] = (half)(sum_t Wg[k][t]*Wu[t][n]); bc = bg@Wu + bu
__global__ void combine_w_kernel(const float* __restrict__ Wg, const float* __restrict__ bg,
                                 const float* __restrict__ Wu, const float* __restrict__ bu) {
    int idx = blockIdx.x * blockDim.x + threadIdx.x;
    if (idx < IN_DIM * OUT_DIM) {
        int n = idx / OUT_DIM;
        int k = idx % OUT_DIM;
        float acc = 0.0f;
        #pragma unroll 8
        for (int t = 0; t < OUT_DIM; t++)
            acc += Wg[k * OUT_DIM + t] * Wu[t * IN_DIM + n];
        d_Wch[idx] = __float2half(acc);
    }
    if (idx < IN_DIM) {
        float acc = bu[idx];
        #pragma unroll 8
        for (int t = 0; t < OUT_DIM; t++)
            acc += bg[t] * Wu[t * IN_DIM + idx];
        d_bc[idx] = acc;
    }
}

// -------- gather (fp16 h/agg): agg[v] = half( sum_{e: dst=v} h[src[e]] ), warp/node, ILP 8 --------
__global__ void gather_kernel(int n_nodes) {
    const int node = blockIdx.x * (blockDim.x >> 5) + (threadIdx.x >> 5);
    const int lane = threadIdx.x & 31;
    if (node >= n_nodes) return;
    const int eb = d_off[node];
    const int cnt = d_indeg[node];

    float4 acc = make_float4(0.f, 0.f, 0.f, 0.f);
    int j = 0;
    for (; j + 8 <= cnt; j += 8) {
        int s[8];
        #pragma unroll
        for (int u = 0; u < 8; u++) s[u] = d_edge_src[eb + j + u];
        uint2 v[8];
        #pragma unroll
        for (int u = 0; u < 8; u++)
            v[u] = *reinterpret_cast<const uint2*>(d_h + (size_t)s[u] * OUT_DIM + lane * 4);
        #pragma unroll
        for (int u = 0; u < 8; u++) {
            float2 f0 = __half22float2(*reinterpret_cast<__half2*>(&v[u].x));
            float2 f1 = __half22float2(*reinterpret_cast<__half2*>(&v[u].y));
            acc.x += f0.x; acc.y += f0.y; acc.z += f1.x; acc.w += f1.y;
        }
    }
    for (; j < cnt; j++) {
        const int s = d_edge_src[eb + j];
        uint2 v = *reinterpret_cast<const uint2*>(d_h + (size_t)s * OUT_DIM + lane * 4);
        float2 f0 = __half22float2(*reinterpret_cast<__half2*>(&v.x));
        float2 f1 = __half22float2(*reinterpret_cast<__half2*>(&v.y));
        acc.x += f0.x; acc.y += f0.y; acc.z += f1.x; acc.w += f1.y;
    }
    uint2 o;
    *reinterpret_cast<__half2*>(&o.x) = __floats2half2_rn(acc.x, acc.y);
    *reinterpret_cast<__half2*>(&o.y) = __floats2half2_rn(acc.z, acc.w);
    *reinterpret_cast<uint2*>(d_agg + (size_t)node * OUT_DIM + lane * 4) = o;
}

// ================= FP16 tensor-core GEMM (m16n8k16), double-buffered =================
// rowscale computed in-epilogue from integer degree: rs = rsqrt(max(deg,1)).
#define HSK 40   // half stride (32 + 8 pad)

template<bool SCALE_AFTER_BIAS, bool CVT_A, bool OUT_HALF>
__global__ __launch_bounds__(256)
void h16_gemm(const float* __restrict__ Af, const __half* __restrict__ Ah,
              const __half* __restrict__ B,
              const float* __restrict__ bias, const int* __restrict__ deg,
              float* __restrict__ Cf, __half* __restrict__ Ch,
              int M, int N, int K) {
    __shared__ __half As[2][128 * HSK];
    __shared__ __half Bs[2][128 * HSK];

    const int tid  = threadIdx.x;
    const int lane = tid & 31;
    const int wid  = tid >> 5;
    const int warp_m = (wid >> 2) * 64;
    const int warp_n = (wid & 3) * 32;

    const int brow = blockIdx.y * 128;
    const int bcol = blockIdx.x * 128;

    const int grp = lane >> 2;
    const int tig = lane & 3;

    const int am  = tid >> 1;
    const int akh = (tid & 1) * 16;

    float4 pa[4];
    auto loadA = [&](int k0) {
        const int gr = brow + am;
        if (gr < M) {
            const float* g = Af + (size_t)gr * K + k0 + akh;
            pa[0] = *reinterpret_cast<const float4*>(g);
            pa[1] = *reinterpret_cast<const float4*>(g + 4);
            pa[2] = *reinterpret_cast<const float4*>(g + 8);
            pa[3] = *reinterpret_cast<const float4*>(g + 12);
        } else {
            pa[0] = pa[1] = pa[2] = pa[3] = make_float4(0.f, 0.f, 0.f, 0.f);
        }
    };
    auto storeA = [&](int s) {
        __half2 h[8];
        h[0] = __floats2half2_rn(pa[0].x, pa[0].y);
        h[1] = __floats2half2_rn(pa[0].z, pa[0].w);
        h[2] = __floats2half2_rn(pa[1].x, pa[1].y);
        h[3] = __floats2half2_rn(pa[1].z, pa[1].w);
        h[4] = __floats2half2_rn(pa[2].x, pa[2].y);
        h[5] = __floats2half2_rn(pa[2].z, pa[2].w);
        h[6] = __floats2half2_rn(pa[3].x, pa[3].y);
        h[7] = __floats2half2_rn(pa[3].z, pa[3].w);
        *reinterpret_cast<uint4*>(&As[s][am * HSK + akh])     = *reinterpret_cast<uint4*>(h);
        *reinterpret_cast<uint4*>(&As[s][am * HSK + akh + 8]) = *reinterpret_cast<uint4*>(h + 4);
    };

    auto issueA16 = [&](int s, int k0) {
        #pragma unroll
        for (int l = 0; l < 2; l++) {
            const int c = tid + l * 256;
            const int m = c >> 2;
            const int kq = (c & 3) * 8;
            const __half* g = Ah + (size_t)(brow + m) * K + k0 + kq;
            uint32_t d = (uint32_t)__cvta_generic_to_shared(&As[s][m * HSK + kq]);
            int vb = (brow + m < M) ? 16 : 0;
            asm volatile("cp.async.cg.shared.global [%0], [%1], 16, %2;"
                         :: "r"(d), "l"(g), "r"(vb));
        }
    };
    auto issueB = [&](int s, int k0) {
        #pragma unroll
        for (int l = 0; l < 2; l++) {
            const int c = tid + l * 256;
            const int n = c >> 2;
            const int kq = (c & 3) * 8;
            const __half* g = B + (size_t)(bcol + n) * K + k0 + kq;
            uint32_t d = (uint32_t)__cvta_generic_to_shared(&Bs[s][n * HSK + kq]);
            asm volatile("cp.async.cg.shared.global [%0], [%1], 16;"
                         :: "r"(d), "l"(g));
        }
    };

    float acc[4][4][4];
    #pragma unroll
    for (int a = 0; a < 4; a++)
        #pragma unroll
        for (int b = 0; b < 4; b++)
            #pragma unroll
            for (int c = 0; c < 4; c++) acc[a][b][c] = 0.f;

    auto compute = [&](int s) {
        #pragma unroll
        for (int kk = 0; kk < 32; kk += 16) {
            uint32_t a[4][4];
            #pragma unroll
            for (int mt = 0; mt < 4; mt++) {
                const int m0 = warp_m + mt * 16;
                a[mt][0] = *reinterpret_cast<const uint32_t*>(&As[s][(m0 + grp    ) * HSK + kk + 2 * tig]);
                a[mt][1] = *reinterpret_cast<const uint32_t*>(&As[s][(m0 + grp + 8) * HSK + kk + 2 * tig]);
                a[mt][2] = *reinterpret_cast<const uint32_t*>(&As[s][(m0 + grp    ) * HSK + kk + 2 * tig + 8]);
                a[mt][3] = *reinterpret_cast<const uint32_t*>(&As[s][(m0 + grp + 8) * HSK + kk + 2 * tig + 8]);
            }
            uint32_t b[4][2];
            #pragma unroll
            for (int nt = 0; nt < 4; nt++) {
                const int n0 = warp_n + nt * 8;
                b[nt][0] = *reinterpret_cast<const uint32_t*>(&Bs[s][(n0 + grp) * HSK + kk + 2 * tig]);
                b[nt][1] = *reinterpret_cast<const uint32_t*>(&Bs[s][(n0 + grp) * HSK + kk + 2 * tig + 8]);
            }
            #pragma unroll
            for (int mt = 0; mt < 4; mt++)
                #pragma unroll
                for (int nt = 0; nt < 4; nt++) {
                    asm volatile(
                        "mma.sync.aligned.m16n8k16.row.col.f32.f16.f16.f32 "
                        "{%0,%1,%2,%3}, {%4,%5,%6,%7}, {%8,%9}, {%0,%1,%2,%3};"
                        : "+f"(acc[mt][nt][0]), "+f"(acc[mt][nt][1]),
                          "+f"(acc[mt][nt][2]), "+f"(acc[mt][nt][3])
                        : "r"(a[mt][0]), "r"(a[mt][1]), "r"(a[mt][2]), "r"(a[mt][3]),
                          "r"(b[nt][0]), "r"(b[nt][1]));
                }
        }
    };

    const int nk = K / 32;
    int buf = 0;
    if (CVT_A) {
        loadA(0);
        issueB(0, 0);
        asm volatile("cp.async.commit_group;");
        storeA(0);
        asm volatile("cp.async.wait_group 0;");
        __syncthreads();
        for (int t = 0; t < nk; t++) {
            if (t + 1 < nk) {
                loadA((t + 1) * 32);
                issueB(buf ^ 1, (t + 1) * 32);
                asm volatile("cp.async.commit_group;");
            }
            compute(buf);
            if (t + 1 < nk) {
                storeA(buf ^ 1);
                asm volatile("cp.async.wait_group 0;");
                __syncthreads();
            }
            buf ^= 1;
        }
    } else {
        issueA16(0, 0);
        issueB(0, 0);
        asm volatile("cp.async.commit_group;");
        asm volatile("cp.async.wait_group 0;");
        __syncthreads();
        for (int t = 0; t < nk; t++) {
            if (t + 1 < nk) {
                issueA16(buf ^ 1, (t + 1) * 32);
                issueB(buf ^ 1, (t + 1) * 32);
                asm volatile("cp.async.commit_group;");
            }
            compute(buf);
            if (t + 1 < nk) {
                asm volatile("cp.async.wait_group 0;");
                __syncthreads();
            }
            buf ^= 1;
        }
    }

    // ---- epilogue (rowscale from integer degree) ----
    #pragma unroll
    for (int mt = 0; mt < 4; mt++) {
        const int r0 = brow + warp_m + mt * 16 + grp;
        const int r1 = r0 + 8;
        const bool ok0 = (r0 < M);
        const bool ok1 = (r1 < M);
        const float s0 = ok0 ? rsqrtf(fmaxf((float)deg[r0], 1.0f)) : 0.f;
        const float s1 = ok1 ? rsqrtf(fmaxf((float)deg[r1], 1.0f)) : 0.f;
        #pragma unroll
        for (int nt = 0; nt < 4; nt++) {
            const int c = bcol + warp_n + nt * 8 + 2 * tig;
            const float bz0 = bias[c], bz1 = bias[c + 1];
            float ox0, oy0, ox1, oy1;
            if (SCALE_AFTER_BIAS) {
                ox0 = (acc[mt][nt][0] + bz0) * s0;
                oy0 = (acc[mt][nt][1] + bz1) * s0;
                ox1 = (acc[mt][nt][2] + bz0) * s1;
                oy1 = (acc[mt][nt][3] + bz1) * s1;
            } else {
                ox0 = fmaf(acc[mt][nt][0], s0, bz0);
                oy0 = fmaf(acc[mt][nt][1], s0, bz1);
                ox1 = fmaf(acc[mt][nt][2], s1, bz0);
                oy1 = fmaf(acc[mt][nt][3], s1, bz1);
            }
            if (OUT_HALF) {
                if (ok0)
                    *reinterpret_cast<__half2*>(Ch + (size_t)r0 * N + c) = __floats2half2_rn(ox0, oy0);
                if (ok1)
                    *reinterpret_cast<__half2*>(Ch + (size_t)r1 * N + c) = __floats2half2_rn(ox1, oy1);
            } else {
                if (ok0)
                    *reinterpret_cast<float2*>(Cf + (size_t)r0 * N + c) = make_float2(ox0, oy0);
                if (ok1)
                    *reinterpret_cast<float2*>(Cf + (size_t)r1 * N + c) = make_float2(ox1, oy1);
            }
        }
    }
}

extern "C" void kernel_launch(void* const* d_in, const int* in_sizes, int n_in,
                              void* d_out, int out_size) {
    const float* features = (const float*)d_in[0];
    const float* Wd       = (const float*)d_in[1];
    const float* bd       = (const float*)d_in[2];
    const float* Wg       = (const float*)d_in[3];
    const float* bg       = (const float*)d_in[4];
    const float* Wu       = (const float*)d_in[5];
    const float* bu       = (const float*)d_in[6];
    const int*   src      = (const int*)d_in[7];
    const int*   dst      = (const int*)d_in[8];
    float*       out      = (float*)d_out;

    const int n_nodes = in_sizes[0] / IN_DIM;
    const int n_edges = in_sizes[7];

    static __half* p_h = nullptr; static __half* p_agg = nullptr;
    static __half* p_Wch = nullptr; static float* p_bc = nullptr;
    static __half* p_Wdh = nullptr;
    static int* p_od = nullptr; static int* p_id = nullptr;
    static cudaStream_t s1;
    static cudaEvent_t ev_fork, ev_deg, ev_wdh, ev_csr;
    if (!p_h) {
        cudaGetSymbolAddress((void**)&p_h,   d_h);
        cudaGetSymbolAddress((void**)&p_agg, d_agg);
        cudaGetSymbolAddress((void**)&p_Wch, d_Wch);
        cudaGetSymbolAddress((void**)&p_bc,  d_bc);
        cudaGetSymbolAddress((void**)&p_Wdh, d_Wdh);
        cudaGetSymbolAddress((void**)&p_od,  d_outdeg);
        cudaGetSymbolAddress((void**)&p_id,  d_indeg);
        cudaStreamCreateWithFlags(&s1, cudaStreamNonBlocking);
        cudaEventCreateWithFlags(&ev_fork, cudaEventDisableTiming);
        cudaEventCreateWithFlags(&ev_deg, cudaEventDisableTiming);
        cudaEventCreateWithFlags(&ev_wdh, cudaEventDisableTiming);
        cudaEventCreateWithFlags(&ev_csr, cudaEventDisableTiming);
    }

    const int nscan_blocks = (n_nodes + 1023) / 1024;

    // fork side stream at capture start
    cudaEventRecord(ev_fork, 0);
    cudaStreamWaitEvent(s1, ev_fork, 0);

    // side stream: wdh (independent of degrees), then CSR chain after degrees
    wdh_kernel<<<(OUT_DIM * IN_DIM + 255) / 256, 256, 0, s1>>>(Wd);
    cudaEventRecord(ev_wdh, s1);

    // main stream: degrees
    zero_deg_kernel<<<(n_nodes + 255) / 256, 256>>>(n_nodes);
    degree_kernel<<<(n_edges + 255) / 256, 256>>>(src, dst, n_edges);
    cudaEventRecord(ev_deg, 0);

    // side stream continues: scan -> CSR fill -> combine_w (needs degrees)
    cudaStreamWaitEvent(s1, ev_deg, 0);
    scan_block_kernel<<<nscan_blocks, 1024, 0, s1>>>(n_nodes);
    scan_sums_kernel<<<1, 32, 0, s1>>>(nscan_blocks);
    scan_add_kernel<<<(n_nodes + 255) / 256, 256, 0, s1>>>(n_nodes);
    csr_fill_kernel<<<(n_edges + 255) / 256, 256, 0, s1>>>(src, dst, n_edges);
    combine_w_kernel<<<(IN_DIM * OUT_DIM + 255) / 256, 256, 0, s1>>>(Wg, bg, Wu, bu);
    cudaEventRecord(ev_csr, s1);

    // main: GEMM1 (waits for Wdh; norm_src computed in epilogue from outdeg)
    cudaStreamWaitEvent(0, ev_wdh, 0);
    {
        dim3 grid(OUT_DIM / 128, (n_nodes + 127) / 128);
        h16_gemm<true, true, true><<<grid, 256>>>(
            features, nullptr, p_Wdh, bd, p_od, nullptr, p_h, n_nodes, OUT_DIM, IN_DIM);
    }

    // join, then gather + GEMM2 (norm_dst in epilogue from indeg)
    cudaStreamWaitEvent(0, ev_csr, 0);
    gather_kernel<<<(n_nodes + 7) / 8, 256>>>(n_nodes);
    {
        dim3 grid(IN_DIM / 128, (n_nodes + 127) / 128);
        h16_gemm<false, false, false><<<grid, 256>>>(
            nullptr, p_agg, p_Wch, p_bc, p_id, out, nullptr, n_nodes, IN_DIM, OUT_DIM);
    }
}

// round 17
// speedup vs baseline: 1.3128x; 1.0136x over previous
#include <cuda_runtime.h>
#include <cuda_fp16.h>
#include <cstdint>

#define N_NODES 100000
#define IN_DIM  768
#define OUT_DIM 128
#define MAX_EDGES 1600000

// -------- scratch (device globals; no allocation allowed) --------
__device__ __half d_h[(size_t)N_NODES * OUT_DIM];    // fp16 h = (features@Wd + bd)*norm_src
__device__ __half d_agg[(size_t)N_NODES * OUT_DIM];  // fp16 gather result
__device__ __half d_Wch[IN_DIM * OUT_DIM];           // (Wg@Wu)^T fp16, [n=768][k=128]
__device__ float  d_bc[IN_DIM];                      // bg @ Wu + bu (fp32)
__device__ __half d_Wdh[OUT_DIM * IN_DIM];           // Wd^T fp16, [n=128][k=768]
__device__ int    d_outdeg[N_NODES];
__device__ int    d_indeg[N_NODES];
__device__ int    d_off[N_NODES + 1];
__device__ int    d_cursor[N_NODES];
__device__ int    d_blocksums[(N_NODES + 1023) / 1024 + 1];
__device__ int    d_edge_src[MAX_EDGES];

// ============ graph/prep kernels ============
__global__ void zero_deg_kernel(int n_nodes) {
    int i = blockIdx.x * blockDim.x + threadIdx.x;
    if (i < n_nodes) { d_outdeg[i] = 0; d_indeg[i] = 0; }
}

__global__ void degree_kernel(const int* __restrict__ src, const int* __restrict__ dst, int n_edges) {
    int i = blockIdx.x * blockDim.x + threadIdx.x;
    if (i < n_edges) {
        atomicAdd(&d_outdeg[src[i]], 1);
        atomicAdd(&d_indeg[dst[i]], 1);
    }
}

// Wd^T fp16: d_Wdh[n*768 + k] = (half)Wd[k*128 + n]
__global__ void wdh_kernel(const float* __restrict__ Wd) {
    int i = blockIdx.x * blockDim.x + threadIdx.x;
    if (i < OUT_DIM * IN_DIM) {
        int n = i / IN_DIM;
        int k = i % IN_DIM;
        d_Wdh[i] = __float2half(Wd[(size_t)k * OUT_DIM + n]);
    }
}

__global__ void scan_block_kernel(int n) {
    __shared__ int sh[1024];
    int gid = blockIdx.x * 1024 + threadIdx.x;
    int v = (gid < n) ? d_indeg[gid] : 0;
    sh[threadIdx.x] = v;
    __syncthreads();
    #pragma unroll
    for (int d = 1; d < 1024; d <<= 1) {
        int t = (threadIdx.x >= d) ? sh[threadIdx.x - d] : 0;
        __syncthreads();
        sh[threadIdx.x] += t;
        __syncthreads();
    }
    if (gid < n) d_off[gid] = sh[threadIdx.x] - v;
    if (threadIdx.x == 1023) d_blocksums[blockIdx.x] = sh[1023];
}

__global__ void scan_sums_kernel(int nb) {
    if (threadIdx.x == 0 && blockIdx.x == 0) {
        int acc = 0;
        for (int i = 0; i < nb; i++) { int v = d_blocksums[i]; d_blocksums[i] = acc; acc += v; }
    }
}

__global__ void scan_add_kernel(int n) {
    int gid = blockIdx.x * blockDim.x + threadIdx.x;
    if (gid < n) {
        d_off[gid] += d_blocksums[gid >> 10];
        d_cursor[gid] = 0;
    }
}

__global__ void csr_fill_kernel(const int* __restrict__ src, const int* __restrict__ dst, int n_edges) {
    int e = blockIdx.x * blockDim.x + threadIdx.x;
    if (e < n_edges) {
        int d = dst[e];
        int pos = d_off[d] + atomicAdd(&d_cursor[d], 1);
        d_edge_src[pos] = src[e];
    }
}

// Wc^T fp16: d_Wch[n*128 + k] = (half)(sum_t Wg[k][t]*Wu[t][n]); bc = bg@Wu + bu
__global__ void combine_w_kernel(const float* __restrict__ Wg, const float* __restrict__ bg,
                                 const float* __restrict__ Wu, const float* __restrict__ bu) {
    int idx = blockIdx.x * blockDim.x + threadIdx.x;
    if (idx < IN_DIM * OUT_DIM) {
        int n = idx / OUT_DIM;
        int k = idx % OUT_DIM;
        float acc = 0.0f;
        #pragma unroll 8
        for (int t = 0; t < OUT_DIM; t++)
            acc += Wg[k * OUT_DIM + t] * Wu[t * IN_DIM + n];
        d_Wch[idx] = __float2half(acc);
    }
    if (idx < IN_DIM) {
        float acc = bu[idx];
        #pragma unroll 8
        for (int t = 0; t < OUT_DIM; t++)
            acc += bg[t] * Wu[t * IN_DIM + idx];
        d_bc[idx] = acc;
    }
}

// -------- gather (fp16 h/agg): agg[v] = half( sum_{e: dst=v} h[src[e]] ), warp/node, ILP 8 --------
__global__ void gather_kernel(int n_nodes) {
    const int node = blockIdx.x * (blockDim.x >> 5) + (threadIdx.x >> 5);
    const int lane = threadIdx.x & 31;
    if (node >= n_nodes) return;
    const int eb = d_off[node];
    const int cnt = d_indeg[node];

    float4 acc = make_float4(0.f, 0.f, 0.f, 0.f);
    int j = 0;
    for (; j + 8 <= cnt; j += 8) {
        int s[8];
        #pragma unroll
        for (int u = 0; u < 8; u++) s[u] = d_edge_src[eb + j + u];
        uint2 v[8];
        #pragma unroll
        for (int u = 0; u < 8; u++)
            v[u] = *reinterpret_cast<const uint2*>(d_h + (size_t)s[u] * OUT_DIM + lane * 4);
        #pragma unroll
        for (int u = 0; u < 8; u++) {
            float2 f0 = __half22float2(*reinterpret_cast<__half2*>(&v[u].x));
            float2 f1 = __half22float2(*reinterpret_cast<__half2*>(&v[u].y));
            acc.x += f0.x; acc.y += f0.y; acc.z += f1.x; acc.w += f1.y;
        }
    }
    for (; j < cnt; j++) {
        const int s = d_edge_src[eb + j];
        uint2 v = *reinterpret_cast<const uint2*>(d_h + (size_t)s * OUT_DIM + lane * 4);
        float2 f0 = __half22float2(*reinterpret_cast<__half2*>(&v.x));
        float2 f1 = __half22float2(*reinterpret_cast<__half2*>(&v.y));
        acc.x += f0.x; acc.y += f0.y; acc.z += f1.x; acc.w += f1.y;
    }
    uint2 o;
    *reinterpret_cast<__half2*>(&o.x) = __floats2half2_rn(acc.x, acc.y);
    *reinterpret_cast<__half2*>(&o.y) = __floats2half2_rn(acc.z, acc.w);
    *reinterpret_cast<uint2*>(d_agg + (size_t)node * OUT_DIM + lane * 4) = o;
}

// ================= FP16 tensor-core GEMM (m16n8k16), ldmatrix fragments =================
// rowscale computed in-epilogue from integer degree: rs = rsqrt(max(deg,1)).
#define HSK 40   // half stride (32 + 8 pad); ldmatrix row addrs conflict-free (r*5 mod 8 bijective)

template<bool SCALE_AFTER_BIAS, bool CVT_A, bool OUT_HALF>
__global__ __launch_bounds__(256)
void h16_gemm(const float* __restrict__ Af, const __half* __restrict__ Ah,
              const __half* __restrict__ B,
              const float* __restrict__ bias, const int* __restrict__ deg,
              float* __restrict__ Cf, __half* __restrict__ Ch,
              int M, int N, int K) {
    __shared__ __half As[2][128 * HSK];
    __shared__ __half Bs[2][128 * HSK];

    const int tid  = threadIdx.x;
    const int lane = tid & 31;
    const int wid  = tid >> 5;
    const int warp_m = (wid >> 2) * 64;
    const int warp_n = (wid & 3) * 32;

    const int brow = blockIdx.y * 128;
    const int bcol = blockIdx.x * 128;

    const int grp = lane >> 2;
    const int tig = lane & 3;

    // ldmatrix per-lane row indices
    const int lm_arow = lane & 15;            // A: rows m0..m0+15
    const int lm_akoff = (lane >> 4) * 8;     // A: +8 halves for lanes 16..31
    const int lm_brow = lane & 7;             // B: rows n0..n0+7 (x2 uses lanes 0..15)
    const int lm_bkoff = ((lane >> 3) & 1) * 8;

    const int am  = tid >> 1;
    const int akh = (tid & 1) * 16;

    float4 pa[4];
    auto loadA = [&](int k0) {
        const int gr = brow + am;
        if (gr < M) {
            const float* g = Af + (size_t)gr * K + k0 + akh;
            pa[0] = *reinterpret_cast<const float4*>(g);
            pa[1] = *reinterpret_cast<const float4*>(g + 4);
            pa[2] = *reinterpret_cast<const float4*>(g + 8);
            pa[3] = *reinterpret_cast<const float4*>(g + 12);
        } else {
            pa[0] = pa[1] = pa[2] = pa[3] = make_float4(0.f, 0.f, 0.f, 0.f);
        }
    };
    auto storeA = [&](int s) {
        __half2 h[8];
        h[0] = __floats2half2_rn(pa[0].x, pa[0].y);
        h[1] = __floats2half2_rn(pa[0].z, pa[0].w);
        h[2] = __floats2half2_rn(pa[1].x, pa[1].y);
        h[3] = __floats2half2_rn(pa[1].z, pa[1].w);
        h[4] = __floats2half2_rn(pa[2].x, pa[2].y);
        h[5] = __floats2half2_rn(pa[2].z, pa[2].w);
        h[6] = __floats2half2_rn(pa[3].x, pa[3].y);
        h[7] = __floats2half2_rn(pa[3].z, pa[3].w);
        *reinterpret_cast<uint4*>(&As[s][am * HSK + akh])     = *reinterpret_cast<uint4*>(h);
        *reinterpret_cast<uint4*>(&As[s][am * HSK + akh + 8]) = *reinterpret_cast<uint4*>(h + 4);
    };

    auto issueA16 = [&](int s, int k0) {
        #pragma unroll
        for (int l = 0; l < 2; l++) {
            const int c = tid + l * 256;
            const int m = c >> 2;
            const int kq = (c & 3) * 8;
            const __half* g = Ah + (size_t)(brow + m) * K + k0 + kq;
            uint32_t d = (uint32_t)__cvta_generic_to_shared(&As[s][m * HSK + kq]);
            int vb = (brow + m < M) ? 16 : 0;
            asm volatile("cp.async.cg.shared.global [%0], [%1], 16, %2;"
                         :: "r"(d), "l"(g), "r"(vb));
        }
    };
    auto issueB = [&](int s, int k0) {
        #pragma unroll
        for (int l = 0; l < 2; l++) {
            const int c = tid + l * 256;
            const int n = c >> 2;
            const int kq = (c & 3) * 8;
            const __half* g = B + (size_t)(bcol + n) * K + k0 + kq;
            uint32_t d = (uint32_t)__cvta_generic_to_shared(&Bs[s][n * HSK + kq]);
            asm volatile("cp.async.cg.shared.global [%0], [%1], 16;"
                         :: "r"(d), "l"(g));
        }
    };

    float acc[4][4][4];
    #pragma unroll
    for (int a = 0; a < 4; a++)
        #pragma unroll
        for (int b = 0; b < 4; b++)
            #pragma unroll
            for (int c = 0; c < 4; c++) acc[a][b][c] = 0.f;

    auto compute = [&](int s) {
        #pragma unroll
        for (int kk = 0; kk < 32; kk += 16) {
            uint32_t a[4][4];
            #pragma unroll
            for (int mt = 0; mt < 4; mt++) {
                const int m0 = warp_m + mt * 16;
                uint32_t addr = (uint32_t)__cvta_generic_to_shared(
                    &As[s][(m0 + lm_arow) * HSK + kk + lm_akoff]);
                asm volatile(
                    "ldmatrix.sync.aligned.m8n8.x4.shared.b16 {%0,%1,%2,%3}, [%4];"
                    : "=r"(a[mt][0]), "=r"(a[mt][1]), "=r"(a[mt][2]), "=r"(a[mt][3])
                    : "r"(addr));
            }
            uint32_t b[4][2];
            #pragma unroll
            for (int nt = 0; nt < 4; nt++) {
                const int n0 = warp_n + nt * 8;
                uint32_t addr = (uint32_t)__cvta_generic_to_shared(
                    &Bs[s][(n0 + lm_brow) * HSK + kk + lm_bkoff]);
                asm volatile(
                    "ldmatrix.sync.aligned.m8n8.x2.shared.b16 {%0,%1}, [%2];"
                    : "=r"(b[nt][0]), "=r"(b[nt][1])
                    : "r"(addr));
            }
            #pragma unroll
            for (int mt = 0; mt < 4; mt++)
                #pragma unroll
                for (int nt = 0; nt < 4; nt++) {
                    asm volatile(
                        "mma.sync.aligned.m16n8k16.row.col.f32.f16.f16.f32 "
                        "{%0,%1,%2,%3}, {%4,%5,%6,%7}, {%8,%9}, {%0,%1,%2,%3};"
                        : "+f"(acc[mt][nt][0]), "+f"(acc[mt][nt][1]),
                          "+f"(acc[mt][nt][2]), "+f"(acc[mt][nt][3])
                        : "r"(a[mt][0]), "r"(a[mt][1]), "r"(a[mt][2]), "r"(a[mt][3]),
                          "r"(b[nt][0]), "r"(b[nt][1]));
                }
        }
    };

    const int nk = K / 32;
    int buf = 0;
    if (CVT_A) {
        loadA(0);
        issueB(0, 0);
        asm volatile("cp.async.commit_group;");
        storeA(0);
        asm volatile("cp.async.wait_group 0;");
        __syncthreads();
        for (int t = 0; t < nk; t++) {
            if (t + 1 < nk) {
                loadA((t + 1) * 32);
                issueB(buf ^ 1, (t + 1) * 32);
                asm volatile("cp.async.commit_group;");
            }
            compute(buf);
            if (t + 1 < nk) {
                storeA(buf ^ 1);
                asm volatile("cp.async.wait_group 0;");
                __syncthreads();
            }
            buf ^= 1;
        }
    } else {
        issueA16(0, 0);
        issueB(0, 0);
        asm volatile("cp.async.commit_group;");
        asm volatile("cp.async.wait_group 0;");
        __syncthreads();
        for (int t = 0; t < nk; t++) {
            if (t + 1 < nk) {
                issueA16(buf ^ 1, (t + 1) * 32);
                issueB(buf ^ 1, (t + 1) * 32);
                asm volatile("cp.async.commit_group;");
            }
            compute(buf);
            if (t + 1 < nk) {
                asm volatile("cp.async.wait_group 0;");
                __syncthreads();
            }
            buf ^= 1;
        }
    }

    // ---- epilogue (rowscale from integer degree) ----
    #pragma unroll
    for (int mt = 0; mt < 4; mt++) {
        const int r0 = brow + warp_m + mt * 16 + grp;
        const int r1 = r0 + 8;
        const bool ok0 = (r0 < M);
        const bool ok1 = (r1 < M);
        const float s0 = ok0 ? rsqrtf(fmaxf((float)deg[r0], 1.0f)) : 0.f;
        const float s1 = ok1 ? rsqrtf(fmaxf((float)deg[r1], 1.0f)) : 0.f;
        #pragma unroll
        for (int nt = 0; nt < 4; nt++) {
            const int c = bcol + warp_n + nt * 8 + 2 * tig;
            const float bz0 = bias[c], bz1 = bias[c + 1];
            float ox0, oy0, ox1, oy1;
            if (SCALE_AFTER_BIAS) {
                ox0 = (acc[mt][nt][0] + bz0) * s0;
                oy0 = (acc[mt][nt][1] + bz1) * s0;
                ox1 = (acc[mt][nt][2] + bz0) * s1;
                oy1 = (acc[mt][nt][3] + bz1) * s1;
            } else {
                ox0 = fmaf(acc[mt][nt][0], s0, bz0);
                oy0 = fmaf(acc[mt][nt][1], s0, bz1);
                ox1 = fmaf(acc[mt][nt][2], s1, bz0);
                oy1 = fmaf(acc[mt][nt][3], s1, bz1);
            }
            if (OUT_HALF) {
                if (ok0)
                    *reinterpret_cast<__half2*>(Ch + (size_t)r0 * N + c) = __floats2half2_rn(ox0, oy0);
                if (ok1)
                    *reinterpret_cast<__half2*>(Ch + (size_t)r1 * N + c) = __floats2half2_rn(ox1, oy1);
            } else {
                if (ok0)
                    __stcs(reinterpret_cast<float2*>(Cf + (size_t)r0 * N + c), make_float2(ox0, oy0));
                if (ok1)
                    __stcs(reinterpret_cast<float2*>(Cf + (size_t)r1 * N + c), make_float2(ox1, oy1));
            }
        }
    }
}

extern "C" void kernel_launch(void* const* d_in, const int* in_sizes, int n_in,
                              void* d_out, int out_size) {
    const float* features = (const float*)d_in[0];
    const float* Wd       = (const float*)d_in[1];
    const float* bd       = (const float*)d_in[2];
    const float* Wg       = (const float*)d_in[3];
    const float* bg       = (const float*)d_in[4];
    const float* Wu       = (const float*)d_in[5];
    const float* bu       = (const float*)d_in[6];
    const int*   src      = (const int*)d_in[7];
    const int*   dst      = (const int*)d_in[8];
    float*       out      = (float*)d_out;

    const int n_nodes = in_sizes[0] / IN_DIM;
    const int n_edges = in_sizes[7];

    static __half* p_h = nullptr; static __half* p_agg = nullptr;
    static __half* p_Wch = nullptr; static float* p_bc = nullptr;
    static __half* p_Wdh = nullptr;
    static int* p_od = nullptr; static int* p_id = nullptr;
    static cudaStream_t s1;
    static cudaEvent_t ev_fork, ev_deg, ev_wdh, ev_csr;
    if (!p_h) {
        cudaGetSymbolAddress((void**)&p_h,   d_h);
        cudaGetSymbolAddress((void**)&p_agg, d_agg);
        cudaGetSymbolAddress((void**)&p_Wch, d_Wch);
        cudaGetSymbolAddress((void**)&p_bc,  d_bc);
        cudaGetSymbolAddress((void**)&p_Wdh, d_Wdh);
        cudaGetSymbolAddress((void**)&p_od,  d_outdeg);
        cudaGetSymbolAddress((void**)&p_id,  d_indeg);
        cudaStreamCreateWithFlags(&s1, cudaStreamNonBlocking);
        cudaEventCreateWithFlags(&ev_fork, cudaEventDisableTiming);
        cudaEventCreateWithFlags(&ev_deg, cudaEventDisableTiming);
        cudaEventCreateWithFlags(&ev_wdh, cudaEventDisableTiming);
        cudaEventCreateWithFlags(&ev_csr, cudaEventDisableTiming);
    }

    const int nscan_blocks = (n_nodes + 1023) / 1024;

    // fork side stream at capture start
    cudaEventRecord(ev_fork, 0);
    cudaStreamWaitEvent(s1, ev_fork, 0);

    // side stream: wdh (independent of degrees), then CSR chain after degrees
    wdh_kernel<<<(OUT_DIM * IN_DIM + 255) / 256, 256, 0, s1>>>(Wd);
    cudaEventRecord(ev_wdh, s1);

    // main stream: degrees
    zero_deg_kernel<<<(n_nodes + 255) / 256, 256>>>(n_nodes);
    degree_kernel<<<(n_edges + 255) / 256, 256>>>(src, dst, n_edges);
    cudaEventRecord(ev_deg, 0);

    // side stream continues: scan -> CSR fill -> combine_w (needs degrees)
    cudaStreamWaitEvent(s1, ev_deg, 0);
    scan_block_kernel<<<nscan_blocks, 1024, 0, s1>>>(n_nodes);
    scan_sums_kernel<<<1, 32, 0, s1>>>(nscan_blocks);
    scan_add_kernel<<<(n_nodes + 255) / 256, 256, 0, s1>>>(n_nodes);
    csr_fill_kernel<<<(n_edges + 255) / 256, 256, 0, s1>>>(src, dst, n_edges);
    combine_w_kernel<<<(IN_DIM * OUT_DIM + 255) / 256, 256, 0, s1>>>(Wg, bg, Wu, bu);
    cudaEventRecord(ev_csr, s1);

    // main: GEMM1 (waits for Wdh; norm_src computed in epilogue from outdeg)
    cudaStreamWaitEvent(0, ev_wdh, 0);
    {
        dim3 grid(OUT_DIM / 128, (n_nodes + 127) / 128);
        h16_gemm<true, true, true><<<grid, 256>>>(
            features, nullptr, p_Wdh, bd, p_od, nullptr, p_h, n_nodes, OUT_DIM, IN_DIM);
    }

    // join, then gather + GEMM2 (norm_dst in epilogue from indeg)
    cudaStreamWaitEvent(0, ev_csr, 0);
    gather_kernel<<<(n_nodes + 7) / 8, 256>>>(n_nodes);
    {
        dim3 grid(IN_DIM / 128, (n_nodes + 127) / 128);
        h16_gemm<false, false, false><<<grid, 256>>>(
            nullptr, p_agg, p_Wch, p_bc, p_id, out, nullptr, n_nodes, IN_DIM, OUT_DIM);
    }
}